// round 2
// baseline (speedup 1.0000x reference)
#include <cuda_runtime.h>
#include <math.h>

#define N_NODES 10000
#define N_EDGES 320000
#define IN_DIM  512
#define CH      128

// ---------------- scratch (device globals; no allocation allowed) ----------------
__device__ float g_h  [N_NODES * CH];   // normalized hidden
__device__ float g_xw [N_NODES * CH];   // (h @ Wg^T) * dinv[row]
__device__ float g_z1 [N_NODES * CH];   // GCN output
__device__ float g_dinv[N_NODES];
__device__ int   g_cnt [N_NODES];
__device__ int   g_pos [N_NODES];
__device__ int   g_off [N_NODES + 1];
__device__ int   g_src [N_EDGES];
__device__ int   g_tgt [N_EDGES];
__device__ int   g_adj [N_EDGES];       // sources sorted by target (CSR payload)
__device__ float g_z2c0[N_NODES];

// ---------------- small utility kernels ----------------
__global__ void zero_kernel() {
    int i = blockIdx.x * blockDim.x + threadIdx.x;
    if (i < N_NODES) { g_cnt[i] = 0; g_pos[i] = 0; }
}

// Detect int64 vs int32 edge buffer: node ids < 10000, so an int64 buffer viewed
// as int32 has zeros at every odd index.
__device__ __forceinline__ bool edges_are_i64(const int* p) {
    bool b = true;
#pragma unroll
    for (int i = 0; i < 8; i++) b = b && (p[2 * i + 1] == 0);
    return b;
}

__global__ void cvt_count_kernel(const int* __restrict__ ep) {
    int e = blockIdx.x * blockDim.x + threadIdx.x;
    if (e >= N_EDGES) return;
    int s, t;
    if (edges_are_i64(ep)) {
        const long long* p = (const long long*)ep;
        s = (int)p[e]; t = (int)p[N_EDGES + e];
    } else {
        s = ep[e]; t = ep[N_EDGES + e];
    }
    g_src[e] = s; g_tgt[e] = t;
    atomicAdd(&g_cnt[t], 1);
}

// single-block exclusive scan of g_cnt -> g_off, plus dinv = rsqrt(cnt+1)
__global__ void scan_kernel() {
    __shared__ int wsum[32];
    int tid = threadIdx.x, lane = tid & 31, wid = tid >> 5;
    int carry = 0;
    for (int base = 0; base < N_NODES; base += 1024) {
        int idx = base + tid;
        int v = (idx < N_NODES) ? g_cnt[idx] : 0;
        int x = v;
#pragma unroll
        for (int d = 1; d < 32; d <<= 1) {
            int y = __shfl_up_sync(0xffffffffu, x, d);
            if (lane >= d) x += y;
        }
        if (lane == 31) wsum[wid] = x;
        __syncthreads();
        if (wid == 0) {
            int s = wsum[lane];
#pragma unroll
            for (int d = 1; d < 32; d <<= 1) {
                int y = __shfl_up_sync(0xffffffffu, s, d);
                if (lane >= d) s += y;
            }
            wsum[lane] = s;
        }
        __syncthreads();
        int offset = wid ? wsum[wid - 1] : 0;
        if (idx < N_NODES) {
            g_off[idx] = carry + offset + x - v;               // exclusive
            g_dinv[idx] = rsqrtf((float)(v + 1));
        }
        carry += wsum[31];
        __syncthreads();
    }
    if (tid == 0) g_off[N_NODES] = carry;
}

// ---------------- tf32 MMA helpers ----------------
__device__ __forceinline__ unsigned f2tf32(float f) {
    unsigned u;
    asm("cvt.rna.tf32.f32 %0, %1;" : "=r"(u) : "f"(f));
    return u;
}

__device__ __forceinline__ void mma_tf32(float c[4], unsigned a0, unsigned a1,
                                         unsigned a2, unsigned a3,
                                         unsigned b0, unsigned b1) {
    asm volatile(
        "mma.sync.aligned.m16n8k8.row.col.f32.tf32.tf32.f32 "
        "{%0,%1,%2,%3}, {%4,%5,%6,%7}, {%8,%9}, {%0,%1,%2,%3};\n"
        : "+f"(c[0]), "+f"(c[1]), "+f"(c[2]), "+f"(c[3])
        : "r"(a0), "r"(a1), "r"(a2), "r"(a3), "r"(b0), "r"(b1));
}

// smem layout: Ws[128][68] floats, then ssq[64] floats
#define WS_STRIDE 68
#define SMEM_FLOATS (128 * WS_STRIDE + 64)

// ---------------- tf32 GEMM block body: out[M,128] = A[M,K] @ W[128,K]^T ----------------
// Block = 256 threads = 8 warps as 2(m) x 4(n). BM=64, BN=128, BK=64.
template <int KDIM, bool NORM, bool ROWSCALE>
__device__ __forceinline__ void gemm_tf32_body(
    const float* __restrict__ A, const float* __restrict__ W,
    const float* __restrict__ bias, const float* __restrict__ rs,
    float* __restrict__ out, int M, float scale, int m0, float* smem) {

    const int tid = threadIdx.x, lane = tid & 31, w = tid >> 5;
    const int gid = lane >> 2, tig = lane & 3;
    const int wm = w & 1, wn = w >> 1;
    const int mbase = m0 + wm * 32;
    const int nbase = wn * 32;
    float* Ws = smem;
    float* ssq = smem + 128 * WS_STRIDE;

    float acc[2][4][4];
#pragma unroll
    for (int i = 0; i < 2; i++)
#pragma unroll
        for (int j = 0; j < 4; j++)
#pragma unroll
            for (int q = 0; q < 4; q++) acc[i][j][q] = 0.f;

    bool vlo[2], vhi[2];
    int rlo[2], rhi[2];
#pragma unroll
    for (int i = 0; i < 2; i++) {
        rlo[i] = mbase + i * 16 + gid;
        rhi[i] = rlo[i] + 8;
        vlo[i] = rlo[i] < M;
        vhi[i] = rhi[i] < M;
    }

    for (int kt = 0; kt < KDIM; kt += 64) {
        __syncthreads();
        // Load W tile [128 n][64 k] into smem
#pragma unroll
        for (int it = 0; it < 8; it++) {
            int idx = tid + it * 256;
            int n = idx >> 4, q = idx & 15;
            float4 v = *(const float4*)(W + (size_t)n * KDIM + kt + q * 4);
            *(float4*)&Ws[n * WS_STRIDE + q * 4] = v;
        }
        __syncthreads();
#pragma unroll
        for (int k8 = 0; k8 < 8; k8++) {
            int kg = kt + k8 * 8;
            unsigned af[2][4];
#pragma unroll
            for (int i = 0; i < 2; i++) {
                const float* Alo = A + (size_t)rlo[i] * KDIM + kg + tig;
                const float* Ahi = A + (size_t)rhi[i] * KDIM + kg + tig;
                float a0 = vlo[i] ? Alo[0] : 0.f;
                float a1 = vhi[i] ? Ahi[0] : 0.f;
                float a2 = vlo[i] ? Alo[4] : 0.f;
                float a3 = vhi[i] ? Ahi[4] : 0.f;
                af[i][0] = f2tf32(a0); af[i][1] = f2tf32(a1);
                af[i][2] = f2tf32(a2); af[i][3] = f2tf32(a3);
            }
#pragma unroll
            for (int j = 0; j < 4; j++) {
                int n = nbase + j * 8 + gid;
                unsigned b0 = f2tf32(Ws[n * WS_STRIDE + k8 * 8 + tig]);
                unsigned b1 = f2tf32(Ws[n * WS_STRIDE + k8 * 8 + tig + 4]);
#pragma unroll
                for (int i = 0; i < 2; i++)
                    mma_tf32(acc[i][j], af[i][0], af[i][1], af[i][2], af[i][3], b0, b1);
            }
        }
    }

    // bias (before norm, matching reference)
    if (bias) {
#pragma unroll
        for (int j = 0; j < 4; j++) {
            int col = nbase + j * 8 + 2 * tig;
            float bv0 = bias[col], bv1 = bias[col + 1];
#pragma unroll
            for (int i = 0; i < 2; i++) {
                acc[i][j][0] += bv0; acc[i][j][1] += bv1;
                acc[i][j][2] += bv0; acc[i][j][3] += bv1;
            }
        }
    }

    float mul_lo[2], mul_hi[2];
#pragma unroll
    for (int i = 0; i < 2; i++) { mul_lo[i] = 1.f; mul_hi[i] = 1.f; }

    if (NORM) {
        __syncthreads();
        if (tid < 64) ssq[tid] = 0.f;
        __syncthreads();
#pragma unroll
        for (int i = 0; i < 2; i++) {
            float plo = 0.f, phi = 0.f;
#pragma unroll
            for (int j = 0; j < 4; j++) {
                plo += acc[i][j][0] * acc[i][j][0] + acc[i][j][1] * acc[i][j][1];
                phi += acc[i][j][2] * acc[i][j][2] + acc[i][j][3] * acc[i][j][3];
            }
            plo += __shfl_xor_sync(0xffffffffu, plo, 1);
            plo += __shfl_xor_sync(0xffffffffu, plo, 2);
            phi += __shfl_xor_sync(0xffffffffu, phi, 1);
            phi += __shfl_xor_sync(0xffffffffu, phi, 2);
            if (tig == 0) {
                atomicAdd(&ssq[wm * 32 + i * 16 + gid], plo);
                atomicAdd(&ssq[wm * 32 + i * 16 + gid + 8], phi);
            }
        }
        __syncthreads();
#pragma unroll
        for (int i = 0; i < 2; i++) {
            mul_lo[i] = scale / fmaxf(sqrtf(ssq[wm * 32 + i * 16 + gid]), 1e-12f);
            mul_hi[i] = scale / fmaxf(sqrtf(ssq[wm * 32 + i * 16 + gid + 8]), 1e-12f);
        }
    }
    if (ROWSCALE) {
#pragma unroll
        for (int i = 0; i < 2; i++) {
            if (vlo[i]) mul_lo[i] *= rs[rlo[i]];
            if (vhi[i]) mul_hi[i] *= rs[rhi[i]];
        }
    }

#pragma unroll
    for (int i = 0; i < 2; i++) {
#pragma unroll
        for (int j = 0; j < 4; j++) {
            int col = nbase + j * 8 + 2 * tig;
            if (vlo[i]) {
                float2 o = make_float2(acc[i][j][0] * mul_lo[i], acc[i][j][1] * mul_lo[i]);
                *(float2*)(out + (size_t)rlo[i] * CH + col) = o;
            }
            if (vhi[i]) {
                float2 o = make_float2(acc[i][j][2] * mul_hi[i], acc[i][j][3] * mul_hi[i]);
                *(float2*)(out + (size_t)rhi[i] * CH + col) = o;
            }
        }
    }
}

// ---------------- z2 body: per row of x2, dot with W22 rows, L2-normalize ----------------
__device__ __forceinline__ void z2_body(const float* __restrict__ x2,
                                        const float* __restrict__ W22,
                                        int i, float* smem) {
    int tid = threadIdx.x, lane = tid & 31, wid = tid >> 5;
    const float4* xr = (const float4*)(x2 + (size_t)i * N_NODES);
    const float4* w0 = (const float4*)W22;
    const float4* w1 = (const float4*)(W22 + N_NODES);
    float s0 = 0.f, s1 = 0.f;
    for (int j = tid; j < N_NODES / 4; j += 256) {
        float4 a = xr[j], b = w0[j], c = w1[j];
        s0 += a.x * b.x + a.y * b.y + a.z * b.z + a.w * b.w;
        s1 += a.x * c.x + a.y * c.y + a.z * c.z + a.w * c.w;
    }
#pragma unroll
    for (int d = 16; d; d >>= 1) {
        s0 += __shfl_xor_sync(0xffffffffu, s0, d);
        s1 += __shfl_xor_sync(0xffffffffu, s1, d);
    }
    float* r0 = smem;
    float* r1 = smem + 8;
    if (lane == 0) { r0[wid] = s0; r1[wid] = s1; }
    __syncthreads();
    if (tid == 0) {
        float y0 = 0.f, y1 = 0.f;
#pragma unroll
        for (int k = 0; k < 8; k++) { y0 += r0[k]; y1 += r1[k]; }
        float n = fmaxf(sqrtf(y0 * y0 + y1 * y1), 1e-12f);
        g_z2c0[i] = 0.8f * y0 / n;
    }
}

// ---------------- fat kernel: gemm1 (tf32) + CSR fill + z2, all independent ----------------
#define GEMM1_BLOCKS 157           // ceil(10000/64)
#define FILL_BLOCKS  64
__global__ __launch_bounds__(256) void fat_kernel(
    const float* __restrict__ x, const float* __restrict__ W2,
    const float* __restrict__ b2,
    const float* __restrict__ x2, const float* __restrict__ W22) {
    __shared__ float smem[SMEM_FLOATS];
    int b = blockIdx.x;
    if (b < GEMM1_BLOCKS) {
        // h = normalize(x @ W2^T + b2) * 1.8
        gemm_tf32_body<IN_DIM, true, false>(x, W2, b2, nullptr, g_h,
                                            N_NODES, 1.8f, b * 64, smem);
    } else if (b < GEMM1_BLOCKS + FILL_BLOCKS) {
        int bb = b - GEMM1_BLOCKS;
        for (int e = threadIdx.x + bb * 256; e < N_EDGES; e += FILL_BLOCKS * 256) {
            int t = g_tgt[e];
            int p = atomicAdd(&g_pos[t], 1);
            g_adj[g_off[t] + p] = g_src[e];
        }
    } else {
        z2_body(x2, W22, b - GEMM1_BLOCKS - FILL_BLOCKS, smem);
    }
}

// ---------------- gemm2 standalone: xw = (h @ Wg^T) * dinv[row] ----------------
__global__ __launch_bounds__(256) void gemm2_kernel(const float* __restrict__ Wg) {
    __shared__ float smem[SMEM_FLOATS];
    gemm_tf32_body<CH, false, true>(g_h, Wg, nullptr, g_dinv, g_xw,
                                    N_NODES, 1.0f, blockIdx.x * 64, smem);
}

// ---------------- GCN gather: z1[i] = dinv[i]*(xws[i] + sum_in xws[s]) + bg ----------------
__global__ void gather_kernel(const float* __restrict__ bg) {
    int i = blockIdx.x;
    int c = threadIdx.x;   // 128 threads, one channel each
    float di = g_dinv[i];
    float acc = g_xw[i * CH + c];
    int s0 = g_off[i], s1 = g_off[i + 1];
    int j = s0;
    // unroll-by-4 for MLP
    for (; j + 4 <= s1; j += 4) {
        int a0 = g_adj[j], a1 = g_adj[j + 1], a2 = g_adj[j + 2], a3 = g_adj[j + 3];
        float v0 = g_xw[a0 * CH + c], v1 = g_xw[a1 * CH + c];
        float v2 = g_xw[a2 * CH + c], v3 = g_xw[a3 * CH + c];
        acc += (v0 + v1) + (v2 + v3);
    }
    for (; j < s1; j++) acc += g_xw[g_adj[j] * CH + c];
    g_z1[i * CH + c] = acc * di + bg[c];
}

// ---------------- decoder: warp per edge ----------------
__global__ void decoder_kernel(float* __restrict__ out) {
    int gw = (blockIdx.x * blockDim.x + threadIdx.x) >> 5;
    int lane = threadIdx.x & 31;
    if (gw >= N_EDGES) return;
    int r = g_src[gw], c = g_tgt[gw];
    const float4* zr = (const float4*)(g_z1 + (size_t)r * CH);
    const float4* zc = (const float4*)(g_z1 + (size_t)c * CH);
    float4 a = zr[lane], b = zc[lane];
    float d = a.x * b.x + a.y * b.y + a.z * b.z + a.w * b.w;
#pragma unroll
    for (int o = 16; o; o >>= 1) d += __shfl_xor_sync(0xffffffffu, d, o);
    if (lane == 0) {
        float vn = g_z2c0[r] + g_z2c0[c];
        float sf = 1.f / (1.f + __expf(-d));
        float sn = 1.f / (1.f + __expf(-vn));
        out[gw] = sf * sf + (1.f - sf) * sn;
    }
}

// ---------------- launch ----------------
extern "C" void kernel_launch(void* const* d_in, const int* in_sizes, int n_in,
                              void* d_out, int out_size) {
    const float* x    = (const float*)d_in[0];
    const float* x2   = (const float*)d_in[1];
    const float* W2   = (const float*)d_in[2];
    const float* b2   = (const float*)d_in[3];
    const float* Wg   = (const float*)d_in[4];
    const float* bg   = (const float*)d_in[5];
    const float* W22  = (const float*)d_in[6];
    const int*   edge = (const int*)d_in[7];
    float* out = (float*)d_out;

    zero_kernel<<<(N_NODES + 255) / 256, 256>>>();
    cvt_count_kernel<<<(N_EDGES + 255) / 256, 256>>>(edge);
    scan_kernel<<<1, 1024>>>();

    // fat kernel: gemm1 + CSR fill + z2 run concurrently
    fat_kernel<<<GEMM1_BLOCKS + FILL_BLOCKS + N_NODES, 256>>>(x, W2, b2, x2, W22);

    gemm2_kernel<<<GEMM1_BLOCKS, 256>>>(Wg);
    gather_kernel<<<N_NODES, CH>>>(bg);
    decoder_kernel<<<(N_EDGES * 32 + 255) / 256, 256>>>(out);
}

// round 3
// speedup vs baseline: 1.4125x; 1.4125x over previous
#include <cuda_runtime.h>
#include <math.h>

#define N_NODES 10000
#define N_EDGES 320000
#define IN_DIM  512
#define CH      128

// ---------------- scratch (device globals; no allocation allowed) ----------------
__device__ float g_h  [N_NODES * CH];   // normalized hidden
__device__ float g_xw [N_NODES * CH];   // (h @ Wg^T) * dinv[row]
__device__ float g_z1 [N_NODES * CH];   // GCN output
__device__ float g_dinv[N_NODES];
__device__ int   g_cnt [N_NODES];
__device__ int   g_pos [N_NODES];
__device__ int   g_off [N_NODES + 1];
__device__ int   g_src [N_EDGES];
__device__ int   g_tgt [N_EDGES];
__device__ int   g_adj [N_EDGES];       // sources sorted by target (CSR payload)
__device__ float g_z2c0[N_NODES];

// ---------------- small utility kernels ----------------
__global__ void zero_kernel() {
    int i = blockIdx.x * blockDim.x + threadIdx.x;
    if (i < N_NODES) { g_cnt[i] = 0; g_pos[i] = 0; }
}

// Detect int64 vs int32 edge buffer: node ids < 10000, so an int64 buffer viewed
// as int32 has zeros at every odd index.
__device__ __forceinline__ bool edges_are_i64(const int* p) {
    bool b = true;
#pragma unroll
    for (int i = 0; i < 8; i++) b = b && (p[2 * i + 1] == 0);
    return b;
}

__global__ void cvt_count_kernel(const int* __restrict__ ep) {
    int e = blockIdx.x * blockDim.x + threadIdx.x;
    if (e >= N_EDGES) return;
    int s, t;
    if (edges_are_i64(ep)) {
        const long long* p = (const long long*)ep;
        s = (int)p[e]; t = (int)p[N_EDGES + e];
    } else {
        s = ep[e]; t = ep[N_EDGES + e];
    }
    g_src[e] = s; g_tgt[e] = t;
    atomicAdd(&g_cnt[t], 1);
}

// single-block exclusive scan of g_cnt -> g_off, plus dinv = rsqrt(cnt+1)
__global__ void scan_kernel() {
    __shared__ int wsum[32];
    int tid = threadIdx.x, lane = tid & 31, wid = tid >> 5;
    int carry = 0;
    for (int base = 0; base < N_NODES; base += 1024) {
        int idx = base + tid;
        int v = (idx < N_NODES) ? g_cnt[idx] : 0;
        int x = v;
#pragma unroll
        for (int d = 1; d < 32; d <<= 1) {
            int y = __shfl_up_sync(0xffffffffu, x, d);
            if (lane >= d) x += y;
        }
        if (lane == 31) wsum[wid] = x;
        __syncthreads();
        if (wid == 0) {
            int s = wsum[lane];
#pragma unroll
            for (int d = 1; d < 32; d <<= 1) {
                int y = __shfl_up_sync(0xffffffffu, s, d);
                if (lane >= d) s += y;
            }
            wsum[lane] = s;
        }
        __syncthreads();
        int offset = wid ? wsum[wid - 1] : 0;
        if (idx < N_NODES) {
            g_off[idx] = carry + offset + x - v;               // exclusive
            g_dinv[idx] = rsqrtf((float)(v + 1));
        }
        carry += wsum[31];
        __syncthreads();
    }
    if (tid == 0) g_off[N_NODES] = carry;
}

// ---------------- tf32 MMA helpers ----------------
__device__ __forceinline__ unsigned f2tf32(float f) {
    unsigned u;
    asm("cvt.rna.tf32.f32 %0, %1;" : "=r"(u) : "f"(f));
    return u;
}

__device__ __forceinline__ void mma_tf32(float c[4], unsigned a0, unsigned a1,
                                         unsigned a2, unsigned a3,
                                         unsigned b0, unsigned b1) {
    asm volatile(
        "mma.sync.aligned.m16n8k8.row.col.f32.tf32.tf32.f32 "
        "{%0,%1,%2,%3}, {%4,%5,%6,%7}, {%8,%9}, {%0,%1,%2,%3};\n"
        : "+f"(c[0]), "+f"(c[1]), "+f"(c[2]), "+f"(c[3])
        : "r"(a0), "r"(a1), "r"(a2), "r"(a3), "r"(b0), "r"(b1));
}

// smem layout: Ws[128][68] floats, then ssq[64] floats
#define WS_STRIDE 68
#define SMEM_FLOATS (128 * WS_STRIDE + 64)

// ---------------- tf32 GEMM block body: out[M,128] = A[M,K] @ W[128,K]^T ----------------
// Block = 256 threads = 8 warps as 2(m) x 4(n). BM=64, BN=128, BK=64.
template <int KDIM, bool NORM, bool ROWSCALE>
__device__ __forceinline__ void gemm_tf32_body(
    const float* __restrict__ A, const float* __restrict__ W,
    const float* __restrict__ bias, const float* __restrict__ rs,
    float* __restrict__ out, int M, float scale, int m0, float* smem) {

    const int tid = threadIdx.x, lane = tid & 31, w = tid >> 5;
    const int gid = lane >> 2, tig = lane & 3;
    const int wm = w & 1, wn = w >> 1;
    const int mbase = m0 + wm * 32;
    const int nbase = wn * 32;
    float* Ws = smem;
    float* ssq = smem + 128 * WS_STRIDE;

    float acc[2][4][4];
#pragma unroll
    for (int i = 0; i < 2; i++)
#pragma unroll
        for (int j = 0; j < 4; j++)
#pragma unroll
            for (int q = 0; q < 4; q++) acc[i][j][q] = 0.f;

    bool vlo[2], vhi[2];
    int rlo[2], rhi[2];
#pragma unroll
    for (int i = 0; i < 2; i++) {
        rlo[i] = mbase + i * 16 + gid;
        rhi[i] = rlo[i] + 8;
        vlo[i] = rlo[i] < M;
        vhi[i] = rhi[i] < M;
    }

    for (int kt = 0; kt < KDIM; kt += 64) {
        __syncthreads();
        // Load W tile [128 n][64 k] into smem
#pragma unroll
        for (int it = 0; it < 8; it++) {
            int idx = tid + it * 256;
            int n = idx >> 4, q = idx & 15;
            float4 v = *(const float4*)(W + (size_t)n * KDIM + kt + q * 4);
            *(float4*)&Ws[n * WS_STRIDE + q * 4] = v;
        }
        __syncthreads();
#pragma unroll
        for (int k8 = 0; k8 < 8; k8++) {
            int kg = kt + k8 * 8;
            unsigned af[2][4];
#pragma unroll
            for (int i = 0; i < 2; i++) {
                const float* Alo = A + (size_t)rlo[i] * KDIM + kg + tig;
                const float* Ahi = A + (size_t)rhi[i] * KDIM + kg + tig;
                float a0 = vlo[i] ? Alo[0] : 0.f;
                float a1 = vhi[i] ? Ahi[0] : 0.f;
                float a2 = vlo[i] ? Alo[4] : 0.f;
                float a3 = vhi[i] ? Ahi[4] : 0.f;
                af[i][0] = f2tf32(a0); af[i][1] = f2tf32(a1);
                af[i][2] = f2tf32(a2); af[i][3] = f2tf32(a3);
            }
#pragma unroll
            for (int j = 0; j < 4; j++) {
                int n = nbase + j * 8 + gid;
                unsigned b0 = f2tf32(Ws[n * WS_STRIDE + k8 * 8 + tig]);
                unsigned b1 = f2tf32(Ws[n * WS_STRIDE + k8 * 8 + tig + 4]);
#pragma unroll
                for (int i = 0; i < 2; i++)
                    mma_tf32(acc[i][j], af[i][0], af[i][1], af[i][2], af[i][3], b0, b1);
            }
        }
    }

    // bias (before norm, matching reference)
    if (bias) {
#pragma unroll
        for (int j = 0; j < 4; j++) {
            int col = nbase + j * 8 + 2 * tig;
            float bv0 = bias[col], bv1 = bias[col + 1];
#pragma unroll
            for (int i = 0; i < 2; i++) {
                acc[i][j][0] += bv0; acc[i][j][1] += bv1;
                acc[i][j][2] += bv0; acc[i][j][3] += bv1;
            }
        }
    }

    float mul_lo[2], mul_hi[2];
#pragma unroll
    for (int i = 0; i < 2; i++) { mul_lo[i] = 1.f; mul_hi[i] = 1.f; }

    if (NORM) {
        __syncthreads();
        if (tid < 64) ssq[tid] = 0.f;
        __syncthreads();
#pragma unroll
        for (int i = 0; i < 2; i++) {
            float plo = 0.f, phi = 0.f;
#pragma unroll
            for (int j = 0; j < 4; j++) {
                plo += acc[i][j][0] * acc[i][j][0] + acc[i][j][1] * acc[i][j][1];
                phi += acc[i][j][2] * acc[i][j][2] + acc[i][j][3] * acc[i][j][3];
            }
            plo += __shfl_xor_sync(0xffffffffu, plo, 1);
            plo += __shfl_xor_sync(0xffffffffu, plo, 2);
            phi += __shfl_xor_sync(0xffffffffu, phi, 1);
            phi += __shfl_xor_sync(0xffffffffu, phi, 2);
            if (tig == 0) {
                atomicAdd(&ssq[wm * 32 + i * 16 + gid], plo);
                atomicAdd(&ssq[wm * 32 + i * 16 + gid + 8], phi);
            }
        }
        __syncthreads();
#pragma unroll
        for (int i = 0; i < 2; i++) {
            mul_lo[i] = scale / fmaxf(sqrtf(ssq[wm * 32 + i * 16 + gid]), 1e-12f);
            mul_hi[i] = scale / fmaxf(sqrtf(ssq[wm * 32 + i * 16 + gid + 8]), 1e-12f);
        }
    }
    if (ROWSCALE) {
#pragma unroll
        for (int i = 0; i < 2; i++) {
            if (vlo[i]) mul_lo[i] *= rs[rlo[i]];
            if (vhi[i]) mul_hi[i] *= rs[rhi[i]];
        }
    }

#pragma unroll
    for (int i = 0; i < 2; i++) {
#pragma unroll
        for (int j = 0; j < 4; j++) {
            int col = nbase + j * 8 + 2 * tig;
            if (vlo[i]) {
                float2 o = make_float2(acc[i][j][0] * mul_lo[i], acc[i][j][1] * mul_lo[i]);
                *(float2*)(out + (size_t)rlo[i] * CH + col) = o;
            }
            if (vhi[i]) {
                float2 o = make_float2(acc[i][j][2] * mul_hi[i], acc[i][j][3] * mul_hi[i]);
                *(float2*)(out + (size_t)rhi[i] * CH + col) = o;
            }
        }
    }
}

// ---------------- z2 body: per row of x2, dot with W22 rows, L2-normalize ----------------
// Latency-tolerant version: 12 independent float4 loads in flight per thread per
// pass (3 passes of 1024 float4 over the 2500-float4 row), so HBM saturates even
// at 2 blocks/SM residency (register-limited by the fused GEMM body).
__device__ __forceinline__ void z2_body(const float* __restrict__ x2,
                                        const float* __restrict__ W22,
                                        int i, float* smem) {
    int tid = threadIdx.x, lane = tid & 31, wid = tid >> 5;
    const float4* __restrict__ xr = (const float4*)(x2 + (size_t)i * N_NODES);
    const float4* __restrict__ w0 = (const float4*)W22;
    const float4* __restrict__ w1 = (const float4*)(W22 + N_NODES);
    const int NV = N_NODES / 4;                 // 2500
    float s0 = 0.f, s1 = 0.f;
#pragma unroll
    for (int base = 0; base < NV; base += 1024) {
        float4 a[4], b[4], c[4];
        int jj[4]; bool v[4];
#pragma unroll
        for (int k = 0; k < 4; k++) {
            jj[k] = base + k * 256 + tid;
            v[k] = jj[k] < NV;
            if (!v[k]) jj[k] = 0;
        }
#pragma unroll
        for (int k = 0; k < 4; k++) a[k] = xr[jj[k]];
#pragma unroll
        for (int k = 0; k < 4; k++) b[k] = w0[jj[k]];
#pragma unroll
        for (int k = 0; k < 4; k++) c[k] = w1[jj[k]];
#pragma unroll
        for (int k = 0; k < 4; k++) {
            if (v[k]) {
                s0 += a[k].x * b[k].x + a[k].y * b[k].y + a[k].z * b[k].z + a[k].w * b[k].w;
                s1 += a[k].x * c[k].x + a[k].y * c[k].y + a[k].z * c[k].z + a[k].w * c[k].w;
            }
        }
    }
#pragma unroll
    for (int d = 16; d; d >>= 1) {
        s0 += __shfl_xor_sync(0xffffffffu, s0, d);
        s1 += __shfl_xor_sync(0xffffffffu, s1, d);
    }
    float* r0 = smem;
    float* r1 = smem + 8;
    if (lane == 0) { r0[wid] = s0; r1[wid] = s1; }
    __syncthreads();
    if (tid == 0) {
        float y0 = 0.f, y1 = 0.f;
#pragma unroll
        for (int k = 0; k < 8; k++) { y0 += r0[k]; y1 += r1[k]; }
        float n = fmaxf(sqrtf(y0 * y0 + y1 * y1), 1e-12f);
        g_z2c0[i] = 0.8f * y0 / n;
    }
}

// ---------------- fat kernel: gemm1 (tf32) + CSR fill + z2, all independent ----------------
#define GEMM1_BLOCKS 157           // ceil(10000/64)
#define FILL_BLOCKS  64
__global__ __launch_bounds__(256) void fat_kernel(
    const float* __restrict__ x, const float* __restrict__ W2,
    const float* __restrict__ b2,
    const float* __restrict__ x2, const float* __restrict__ W22) {
    __shared__ float smem[SMEM_FLOATS];
    int b = blockIdx.x;
    if (b < GEMM1_BLOCKS) {
        // h = normalize(x @ W2^T + b2) * 1.8
        gemm_tf32_body<IN_DIM, true, false>(x, W2, b2, nullptr, g_h,
                                            N_NODES, 1.8f, b * 64, smem);
    } else if (b < GEMM1_BLOCKS + FILL_BLOCKS) {
        int bb = b - GEMM1_BLOCKS;
        for (int e = threadIdx.x + bb * 256; e < N_EDGES; e += FILL_BLOCKS * 256) {
            int t = g_tgt[e];
            int p = atomicAdd(&g_pos[t], 1);
            g_adj[g_off[t] + p] = g_src[e];
        }
    } else {
        z2_body(x2, W22, b - GEMM1_BLOCKS - FILL_BLOCKS, smem);
    }
}

// ---------------- gemm2 standalone: xw = (h @ Wg^T) * dinv[row] ----------------
__global__ __launch_bounds__(256) void gemm2_kernel(const float* __restrict__ Wg) {
    __shared__ float smem[SMEM_FLOATS];
    gemm_tf32_body<CH, false, true>(g_h, Wg, nullptr, g_dinv, g_xw,
                                    N_NODES, 1.0f, blockIdx.x * 64, smem);
}

// ---------------- GCN gather: z1[i] = dinv[i]*(xws[i] + sum_in xws[s]) + bg ----------------
__global__ void gather_kernel(const float* __restrict__ bg) {
    int i = blockIdx.x;
    int c = threadIdx.x;   // 128 threads, one channel each
    float di = g_dinv[i];
    float acc = g_xw[i * CH + c];
    int s0 = g_off[i], s1 = g_off[i + 1];
    int j = s0;
    // unroll-by-4 for MLP
    for (; j + 4 <= s1; j += 4) {
        int a0 = g_adj[j], a1 = g_adj[j + 1], a2 = g_adj[j + 2], a3 = g_adj[j + 3];
        float v0 = g_xw[a0 * CH + c], v1 = g_xw[a1 * CH + c];
        float v2 = g_xw[a2 * CH + c], v3 = g_xw[a3 * CH + c];
        acc += (v0 + v1) + (v2 + v3);
    }
    for (; j < s1; j++) acc += g_xw[g_adj[j] * CH + c];
    g_z1[i * CH + c] = acc * di + bg[c];
}

// ---------------- decoder: warp per edge ----------------
__global__ void decoder_kernel(float* __restrict__ out) {
    int gw = (blockIdx.x * blockDim.x + threadIdx.x) >> 5;
    int lane = threadIdx.x & 31;
    if (gw >= N_EDGES) return;
    int r = g_src[gw], c = g_tgt[gw];
    const float4* zr = (const float4*)(g_z1 + (size_t)r * CH);
    const float4* zc = (const float4*)(g_z1 + (size_t)c * CH);
    float4 a = zr[lane], b = zc[lane];
    float d = a.x * b.x + a.y * b.y + a.z * b.z + a.w * b.w;
#pragma unroll
    for (int o = 16; o; o >>= 1) d += __shfl_xor_sync(0xffffffffu, d, o);
    if (lane == 0) {
        float vn = g_z2c0[r] + g_z2c0[c];
        float sf = 1.f / (1.f + __expf(-d));
        float sn = 1.f / (1.f + __expf(-vn));
        out[gw] = sf * sf + (1.f - sf) * sn;
    }
}

// ---------------- launch ----------------
extern "C" void kernel_launch(void* const* d_in, const int* in_sizes, int n_in,
                              void* d_out, int out_size) {
    const float* x    = (const float*)d_in[0];
    const float* x2   = (const float*)d_in[1];
    const float* W2   = (const float*)d_in[2];
    const float* b2   = (const float*)d_in[3];
    const float* Wg   = (const float*)d_in[4];
    const float* bg   = (const float*)d_in[5];
    const float* W22  = (const float*)d_in[6];
    const int*   edge = (const int*)d_in[7];
    float* out = (float*)d_out;

    zero_kernel<<<(N_NODES + 255) / 256, 256>>>();
    cvt_count_kernel<<<(N_EDGES + 255) / 256, 256>>>(edge);
    scan_kernel<<<1, 1024>>>();

    // fat kernel: gemm1 + CSR fill + z2 run concurrently
    fat_kernel<<<GEMM1_BLOCKS + FILL_BLOCKS + N_NODES, 256>>>(x, W2, b2, x2, W22);

    gemm2_kernel<<<GEMM1_BLOCKS, 256>>>(Wg);
    gather_kernel<<<N_NODES, CH>>>(bg);
    decoder_kernel<<<(N_EDGES * 32 + 255) / 256, 256>>>(out);
}

// round 4
// speedup vs baseline: 1.4980x; 1.0605x over previous
#include <cuda_runtime.h>
#include <math.h>

#define N_NODES 10000
#define N_EDGES 320000
#define IN_DIM  512
#define CH      128

// ---------------- scratch (device globals; zero-initialized at load) ----------------
__device__ float g_h  [N_NODES * CH];   // normalized hidden
__device__ float g_xw [N_NODES * CH];   // (h @ Wg^T) * dinv[row]
__device__ float g_z1 [N_NODES * CH];   // GCN output
__device__ float g_dinv[N_NODES];
__device__ int   g_cnt [N_NODES];       // re-zeroed by decoder each run
__device__ int   g_pos [N_NODES];       // re-zeroed by decoder each run
__device__ int   g_off [N_NODES + 1];
__device__ int   g_src [N_EDGES];
__device__ int   g_tgt [N_EDGES];
__device__ int   g_adj [N_EDGES];       // sources grouped by target (CSR payload)
__device__ int   g_eid [N_EDGES];       // original edge id per CSR slot
__device__ float g_z2c0[N_NODES];

// z2 row partition across the three fat kernels
#define Z2A 3800
#define Z2B 3400
#define Z2C 2800   // Z2A+Z2B+Z2C == N_NODES

// ---------------- setup kernels ----------------
__device__ __forceinline__ bool edges_are_i64(const int* p) {
    bool b = true;
#pragma unroll
    for (int i = 0; i < 8; i++) b = b && (p[2 * i + 1] == 0);
    return b;
}

__global__ void cvt_count_kernel(const int* __restrict__ ep) {
    int e = blockIdx.x * blockDim.x + threadIdx.x;
    if (e >= N_EDGES) return;
    int s, t;
    if (edges_are_i64(ep)) {
        const long long* p = (const long long*)ep;
        s = (int)p[e]; t = (int)p[N_EDGES + e];
    } else {
        s = ep[e]; t = ep[N_EDGES + e];
    }
    g_src[e] = s; g_tgt[e] = t;
    atomicAdd(&g_cnt[t], 1);
}

// single-block exclusive scan of g_cnt -> g_off, plus dinv = rsqrt(cnt+1)
__global__ void scan_kernel() {
    __shared__ int wsum[32];
    int tid = threadIdx.x, lane = tid & 31, wid = tid >> 5;
    int carry = 0;
    for (int base = 0; base < N_NODES; base += 1024) {
        int idx = base + tid;
        int v = (idx < N_NODES) ? g_cnt[idx] : 0;
        int x = v;
#pragma unroll
        for (int d = 1; d < 32; d <<= 1) {
            int y = __shfl_up_sync(0xffffffffu, x, d);
            if (lane >= d) x += y;
        }
        if (lane == 31) wsum[wid] = x;
        __syncthreads();
        if (wid == 0) {
            int s = wsum[lane];
#pragma unroll
            for (int d = 1; d < 32; d <<= 1) {
                int y = __shfl_up_sync(0xffffffffu, s, d);
                if (lane >= d) s += y;
            }
            wsum[lane] = s;
        }
        __syncthreads();
        int offset = wid ? wsum[wid - 1] : 0;
        if (idx < N_NODES) {
            g_off[idx] = carry + offset + x - v;
            g_dinv[idx] = rsqrtf((float)(v + 1));
        }
        carry += wsum[31];
        __syncthreads();
    }
    if (tid == 0) g_off[N_NODES] = carry;
}

// ---------------- tf32 MMA helpers ----------------
__device__ __forceinline__ unsigned f2tf32(float f) {
    unsigned u;
    asm("cvt.rna.tf32.f32 %0, %1;" : "=r"(u) : "f"(f));
    return u;
}

__device__ __forceinline__ void mma_tf32(float c[4], unsigned a0, unsigned a1,
                                         unsigned a2, unsigned a3,
                                         unsigned b0, unsigned b1) {
    asm volatile(
        "mma.sync.aligned.m16n8k8.row.col.f32.tf32.tf32.f32 "
        "{%0,%1,%2,%3}, {%4,%5,%6,%7}, {%8,%9}, {%0,%1,%2,%3};\n"
        : "+f"(c[0]), "+f"(c[1]), "+f"(c[2]), "+f"(c[3])
        : "r"(a0), "r"(a1), "r"(a2), "r"(a3), "r"(b0), "r"(b1));
}

#define WS_STRIDE 68
#define SMEM_FLOATS (128 * WS_STRIDE + 64)

// ---------------- tf32 GEMM block body: out[M,128] = A[M,K] @ W[128,K]^T ----------------
template <int KDIM, bool NORM, bool ROWSCALE>
__device__ __forceinline__ void gemm_tf32_body(
    const float* __restrict__ A, const float* __restrict__ W,
    const float* __restrict__ bias, const float* __restrict__ rs,
    float* __restrict__ out, int M, float scale, int m0, float* smem) {

    const int tid = threadIdx.x, lane = tid & 31, w = tid >> 5;
    const int gid = lane >> 2, tig = lane & 3;
    const int wm = w & 1, wn = w >> 1;
    const int mbase = m0 + wm * 32;
    const int nbase = wn * 32;
    float* Ws = smem;
    float* ssq = smem + 128 * WS_STRIDE;

    float acc[2][4][4];
#pragma unroll
    for (int i = 0; i < 2; i++)
#pragma unroll
        for (int j = 0; j < 4; j++)
#pragma unroll
            for (int q = 0; q < 4; q++) acc[i][j][q] = 0.f;

    bool vlo[2], vhi[2];
    int rlo[2], rhi[2];
#pragma unroll
    for (int i = 0; i < 2; i++) {
        rlo[i] = mbase + i * 16 + gid;
        rhi[i] = rlo[i] + 8;
        vlo[i] = rlo[i] < M;
        vhi[i] = rhi[i] < M;
    }

    for (int kt = 0; kt < KDIM; kt += 64) {
        __syncthreads();
#pragma unroll
        for (int it = 0; it < 8; it++) {
            int idx = tid + it * 256;
            int n = idx >> 4, q = idx & 15;
            float4 v = *(const float4*)(W + (size_t)n * KDIM + kt + q * 4);
            *(float4*)&Ws[n * WS_STRIDE + q * 4] = v;
        }
        __syncthreads();
#pragma unroll
        for (int k8 = 0; k8 < 8; k8++) {
            int kg = kt + k8 * 8;
            unsigned af[2][4];
#pragma unroll
            for (int i = 0; i < 2; i++) {
                const float* Alo = A + (size_t)rlo[i] * KDIM + kg + tig;
                const float* Ahi = A + (size_t)rhi[i] * KDIM + kg + tig;
                float a0 = vlo[i] ? Alo[0] : 0.f;
                float a1 = vhi[i] ? Ahi[0] : 0.f;
                float a2 = vlo[i] ? Alo[4] : 0.f;
                float a3 = vhi[i] ? Ahi[4] : 0.f;
                af[i][0] = f2tf32(a0); af[i][1] = f2tf32(a1);
                af[i][2] = f2tf32(a2); af[i][3] = f2tf32(a3);
            }
#pragma unroll
            for (int j = 0; j < 4; j++) {
                int n = nbase + j * 8 + gid;
                unsigned b0 = f2tf32(Ws[n * WS_STRIDE + k8 * 8 + tig]);
                unsigned b1 = f2tf32(Ws[n * WS_STRIDE + k8 * 8 + tig + 4]);
#pragma unroll
                for (int i = 0; i < 2; i++)
                    mma_tf32(acc[i][j], af[i][0], af[i][1], af[i][2], af[i][3], b0, b1);
            }
        }
    }

    if (bias) {
#pragma unroll
        for (int j = 0; j < 4; j++) {
            int col = nbase + j * 8 + 2 * tig;
            float bv0 = bias[col], bv1 = bias[col + 1];
#pragma unroll
            for (int i = 0; i < 2; i++) {
                acc[i][j][0] += bv0; acc[i][j][1] += bv1;
                acc[i][j][2] += bv0; acc[i][j][3] += bv1;
            }
        }
    }

    float mul_lo[2], mul_hi[2];
#pragma unroll
    for (int i = 0; i < 2; i++) { mul_lo[i] = 1.f; mul_hi[i] = 1.f; }

    if (NORM) {
        __syncthreads();
        if (tid < 64) ssq[tid] = 0.f;
        __syncthreads();
#pragma unroll
        for (int i = 0; i < 2; i++) {
            float plo = 0.f, phi = 0.f;
#pragma unroll
            for (int j = 0; j < 4; j++) {
                plo += acc[i][j][0] * acc[i][j][0] + acc[i][j][1] * acc[i][j][1];
                phi += acc[i][j][2] * acc[i][j][2] + acc[i][j][3] * acc[i][j][3];
            }
            plo += __shfl_xor_sync(0xffffffffu, plo, 1);
            plo += __shfl_xor_sync(0xffffffffu, plo, 2);
            phi += __shfl_xor_sync(0xffffffffu, phi, 1);
            phi += __shfl_xor_sync(0xffffffffu, phi, 2);
            if (tig == 0) {
                atomicAdd(&ssq[wm * 32 + i * 16 + gid], plo);
                atomicAdd(&ssq[wm * 32 + i * 16 + gid + 8], phi);
            }
        }
        __syncthreads();
#pragma unroll
        for (int i = 0; i < 2; i++) {
            mul_lo[i] = scale / fmaxf(sqrtf(ssq[wm * 32 + i * 16 + gid]), 1e-12f);
            mul_hi[i] = scale / fmaxf(sqrtf(ssq[wm * 32 + i * 16 + gid + 8]), 1e-12f);
        }
    }
    if (ROWSCALE) {
#pragma unroll
        for (int i = 0; i < 2; i++) {
            if (vlo[i]) mul_lo[i] *= rs[rlo[i]];
            if (vhi[i]) mul_hi[i] *= rs[rhi[i]];
        }
    }

#pragma unroll
    for (int i = 0; i < 2; i++) {
#pragma unroll
        for (int j = 0; j < 4; j++) {
            int col = nbase + j * 8 + 2 * tig;
            if (vlo[i]) {
                float2 o = make_float2(acc[i][j][0] * mul_lo[i], acc[i][j][1] * mul_lo[i]);
                *(float2*)(out + (size_t)rlo[i] * CH + col) = o;
            }
            if (vhi[i]) {
                float2 o = make_float2(acc[i][j][2] * mul_hi[i], acc[i][j][3] * mul_hi[i]);
                *(float2*)(out + (size_t)rhi[i] * CH + col) = o;
            }
        }
    }
}

// ---------------- z2 body: double-buffered DRAM stream ----------------
// Pass structure (3 passes of 1024 float4 over 2500): prefetch pass p+1's x2
// loads BEFORE the FMA phase of pass p so DRAM stays busy through compute.
__device__ __forceinline__ void z2_body(const float* __restrict__ x2,
                                        const float* __restrict__ W22,
                                        int i, float* smem) {
    int tid = threadIdx.x, lane = tid & 31, wid = tid >> 5;
    const float4* __restrict__ xr = (const float4*)(x2 + (size_t)i * N_NODES);
    const float4* __restrict__ w0 = (const float4*)W22;
    const float4* __restrict__ w1 = (const float4*)(W22 + N_NODES);
    const int NV = N_NODES / 4;                 // 2500
    float s0 = 0.f, s1 = 0.f;

    float4 aC[4], aN[4];
#pragma unroll
    for (int k = 0; k < 4; k++) aC[k] = xr[k * 256 + tid];  // pass 0 (all < 1024 valid)

#pragma unroll
    for (int p = 0; p < 3; p++) {
        int base = p * 1024;
        float4 b[4], c[4];
        int jj[4]; bool v[4];
#pragma unroll
        for (int k = 0; k < 4; k++) {
            jj[k] = base + k * 256 + tid;
            v[k] = jj[k] < NV;
            if (!v[k]) jj[k] = 0;
        }
#pragma unroll
        for (int k = 0; k < 4; k++) b[k] = w0[jj[k]];
#pragma unroll
        for (int k = 0; k < 4; k++) c[k] = w1[jj[k]];
        if (p < 2) {
            int nb = base + 1024;
#pragma unroll
            for (int k = 0; k < 4; k++) {
                int j = nb + k * 256 + tid;
                aN[k] = (j < NV) ? xr[j] : make_float4(0.f, 0.f, 0.f, 0.f);
            }
        }
#pragma unroll
        for (int k = 0; k < 4; k++) {
            if (v[k]) {
                s0 += aC[k].x * b[k].x + aC[k].y * b[k].y + aC[k].z * b[k].z + aC[k].w * b[k].w;
                s1 += aC[k].x * c[k].x + aC[k].y * c[k].y + aC[k].z * c[k].z + aC[k].w * c[k].w;
            }
        }
#pragma unroll
        for (int k = 0; k < 4; k++) aC[k] = aN[k];
    }

#pragma unroll
    for (int d = 16; d; d >>= 1) {
        s0 += __shfl_xor_sync(0xffffffffu, s0, d);
        s1 += __shfl_xor_sync(0xffffffffu, s1, d);
    }
    float* r0 = smem;
    float* r1 = smem + 8;
    if (lane == 0) { r0[wid] = s0; r1[wid] = s1; }
    __syncthreads();
    if (tid == 0) {
        float y0 = 0.f, y1 = 0.f;
#pragma unroll
        for (int k = 0; k < 8; k++) { y0 += r0[k]; y1 += r1[k]; }
        float n = fmaxf(sqrtf(y0 * y0 + y1 * y1), 1e-12f);
        g_z2c0[i] = 0.8f * y0 / n;
    }
}

// ---------------- fatA: gemm1 + CSR fill + z2[0, Z2A) ----------------
#define GEMM_BLOCKS 157            // ceil(10000/64)
#define FILL_BLOCKS 64
__global__ __launch_bounds__(256) void fatA_kernel(
    const float* __restrict__ x, const float* __restrict__ W2,
    const float* __restrict__ b2,
    const float* __restrict__ x2, const float* __restrict__ W22) {
    __shared__ float smem[SMEM_FLOATS];
    int b = blockIdx.x;
    if (b < GEMM_BLOCKS) {
        gemm_tf32_body<IN_DIM, true, false>(x, W2, b2, nullptr, g_h,
                                            N_NODES, 1.8f, b * 64, smem);
    } else if (b < GEMM_BLOCKS + FILL_BLOCKS) {
        int bb = b - GEMM_BLOCKS;
        for (int e = threadIdx.x + bb * 256; e < N_EDGES; e += FILL_BLOCKS * 256) {
            int t = g_tgt[e];
            int p = atomicAdd(&g_pos[t], 1);
            int w = g_off[t] + p;
            g_adj[w] = g_src[e];
            g_eid[w] = e;
        }
    } else {
        z2_body(x2, W22, b - GEMM_BLOCKS - FILL_BLOCKS, smem);
    }
}

// ---------------- fatB: gemm2 + z2[Z2A, Z2A+Z2B) ----------------
__global__ __launch_bounds__(256) void fatB_kernel(
    const float* __restrict__ Wg,
    const float* __restrict__ x2, const float* __restrict__ W22) {
    __shared__ float smem[SMEM_FLOATS];
    int b = blockIdx.x;
    if (b < GEMM_BLOCKS) {
        gemm_tf32_body<CH, false, true>(g_h, Wg, nullptr, g_dinv, g_xw,
                                        N_NODES, 1.0f, b * 64, smem);
    } else {
        z2_body(x2, W22, Z2A + (b - GEMM_BLOCKS), smem);
    }
}

// ---------------- gather body: z1[i] = dinv[i]*(xw_scaled sum) + bg ----------------
__device__ __forceinline__ void gather_body(const float* __restrict__ bg,
                                            int i, int c) {
    float di = g_dinv[i];
    float acc = g_xw[i * CH + c];
    int s0 = g_off[i], s1 = g_off[i + 1];
    int j = s0;
    for (; j + 4 <= s1; j += 4) {
        int a0 = g_adj[j], a1 = g_adj[j + 1], a2 = g_adj[j + 2], a3 = g_adj[j + 3];
        float v0 = g_xw[a0 * CH + c], v1 = g_xw[a1 * CH + c];
        float v2 = g_xw[a2 * CH + c], v3 = g_xw[a3 * CH + c];
        acc += (v0 + v1) + (v2 + v3);
    }
    for (; j < s1; j++) acc += g_xw[g_adj[j] * CH + c];
    g_z1[i * CH + c] = acc * di + bg[c];
}

// ---------------- fatC: gather (2 nodes per block) + z2[Z2A+Z2B, 10000) ----------------
#define GATHER_BLOCKS 5000
__global__ __launch_bounds__(256) void fatC_kernel(
    const float* __restrict__ bg,
    const float* __restrict__ x2, const float* __restrict__ W22) {
    __shared__ float smem[SMEM_FLOATS];
    int b = blockIdx.x;
    if (b < GATHER_BLOCKS) {
        int node = b * 2 + (threadIdx.x >> 7);
        gather_body(bg, node, threadIdx.x & 127);
    } else {
        z2_body(x2, W22, Z2A + Z2B + (b - GATHER_BLOCKS), smem);
    }
}

// ---------------- decoder: warp per target node, CSR order, out[eid] ----------------
__global__ __launch_bounds__(256) void decoder_kernel(float* __restrict__ out) {
    int gtid = blockIdx.x * blockDim.x + threadIdx.x;
    // restore cnt/pos to zero for the next graph replay
    if (gtid < N_NODES) { g_cnt[gtid] = 0; g_pos[gtid] = 0; }

    int node = gtid >> 5;
    int lane = threadIdx.x & 31;
    if (node >= N_NODES) return;
    float4 zc = *(const float4*)(g_z1 + (size_t)node * CH + lane * 4);
    float zc0 = g_z2c0[node];
    int s0 = g_off[node], s1 = g_off[node + 1];
    for (int j = s0; j < s1; j++) {
        int s = g_adj[j];
        const float4 a = *(const float4*)(g_z1 + (size_t)s * CH + lane * 4);
        float d = a.x * zc.x + a.y * zc.y + a.z * zc.z + a.w * zc.w;
#pragma unroll
        for (int o = 16; o; o >>= 1) d += __shfl_xor_sync(0xffffffffu, d, o);
        if (lane == 0) {
            float vn = g_z2c0[s] + zc0;
            float sf = 1.f / (1.f + __expf(-d));
            float sn = 1.f / (1.f + __expf(-vn));
            out[g_eid[j]] = sf * sf + (1.f - sf) * sn;
        }
    }
}

// ---------------- launch ----------------
extern "C" void kernel_launch(void* const* d_in, const int* in_sizes, int n_in,
                              void* d_out, int out_size) {
    const float* x    = (const float*)d_in[0];
    const float* x2   = (const float*)d_in[1];
    const float* W2   = (const float*)d_in[2];
    const float* b2   = (const float*)d_in[3];
    const float* Wg   = (const float*)d_in[4];
    const float* bg   = (const float*)d_in[5];
    const float* W22  = (const float*)d_in[6];
    const int*   edge = (const int*)d_in[7];
    float* out = (float*)d_out;

    cvt_count_kernel<<<(N_EDGES + 255) / 256, 256>>>(edge);
    scan_kernel<<<1, 1024>>>();

    fatA_kernel<<<GEMM_BLOCKS + FILL_BLOCKS + Z2A, 256>>>(x, W2, b2, x2, W22);
    fatB_kernel<<<GEMM_BLOCKS + Z2B, 256>>>(Wg, x2, W22);
    fatC_kernel<<<GATHER_BLOCKS + Z2C, 256>>>(bg, x2, W22);

    decoder_kernel<<<(N_NODES * 32 + 255) / 256, 256>>>(out);
}

// round 5
// speedup vs baseline: 1.6357x; 1.0919x over previous
#include <cuda_runtime.h>
#include <math.h>

#define N_NODES 10000
#define N_EDGES 320000
#define IN_DIM  512
#define CH      128

// ---------------- scratch (device globals; zero-initialized at load) ----------------
__device__ float g_h  [N_NODES * CH];
__device__ float g_xw [N_NODES * CH];
__device__ float g_z1 [N_NODES * CH];
__device__ float g_dinv[N_NODES];
__device__ int   g_cnt [N_NODES];       // re-zeroed by decoder each run
__device__ int   g_pos [N_NODES];       // re-zeroed by decoder each run
__device__ int   g_off [N_NODES + 1];
__device__ int   g_src [N_EDGES];
__device__ int   g_tgt [N_EDGES];
__device__ int   g_adj [N_EDGES];
__device__ int   g_eid [N_EDGES];
__device__ float g_z2c0[N_NODES];

// z2: 4 rows per block; block partition across the three fat kernels
#define Z2A_BLK 950    // rows [0, 3800)
#define Z2B_BLK 850    // rows [3800, 7200)
#define Z2C_BLK 700    // rows [7200, 10000)

// ---------------- setup kernels ----------------
__device__ __forceinline__ bool edges_are_i64(const int* p) {
    bool b = true;
#pragma unroll
    for (int i = 0; i < 8; i++) b = b && (p[2 * i + 1] == 0);
    return b;
}

__global__ void cvt_count_kernel(const int* __restrict__ ep) {
    int e = blockIdx.x * blockDim.x + threadIdx.x;
    if (e >= N_EDGES) return;
    int s, t;
    if (edges_are_i64(ep)) {
        const long long* p = (const long long*)ep;
        s = (int)p[e]; t = (int)p[N_EDGES + e];
    } else {
        s = ep[e]; t = ep[N_EDGES + e];
    }
    g_src[e] = s; g_tgt[e] = t;
    atomicAdd(&g_cnt[t], 1);
}

__global__ void scan_kernel() {
    __shared__ int wsum[32];
    int tid = threadIdx.x, lane = tid & 31, wid = tid >> 5;
    int carry = 0;
    for (int base = 0; base < N_NODES; base += 1024) {
        int idx = base + tid;
        int v = (idx < N_NODES) ? g_cnt[idx] : 0;
        int x = v;
#pragma unroll
        for (int d = 1; d < 32; d <<= 1) {
            int y = __shfl_up_sync(0xffffffffu, x, d);
            if (lane >= d) x += y;
        }
        if (lane == 31) wsum[wid] = x;
        __syncthreads();
        if (wid == 0) {
            int s = wsum[lane];
#pragma unroll
            for (int d = 1; d < 32; d <<= 1) {
                int y = __shfl_up_sync(0xffffffffu, s, d);
                if (lane >= d) s += y;
            }
            wsum[lane] = s;
        }
        __syncthreads();
        int offset = wid ? wsum[wid - 1] : 0;
        if (idx < N_NODES) {
            g_off[idx] = carry + offset + x - v;
            g_dinv[idx] = rsqrtf((float)(v + 1));
        }
        carry += wsum[31];
        __syncthreads();
    }
    if (tid == 0) g_off[N_NODES] = carry;
}

// ---------------- tf32 MMA helpers ----------------
__device__ __forceinline__ unsigned f2tf32(float f) {
    unsigned u;
    asm("cvt.rna.tf32.f32 %0, %1;" : "=r"(u) : "f"(f));
    return u;
}

__device__ __forceinline__ void mma_tf32(float c[4], unsigned a0, unsigned a1,
                                         unsigned a2, unsigned a3,
                                         unsigned b0, unsigned b1) {
    asm volatile(
        "mma.sync.aligned.m16n8k8.row.col.f32.tf32.tf32.f32 "
        "{%0,%1,%2,%3}, {%4,%5,%6,%7}, {%8,%9}, {%0,%1,%2,%3};\n"
        : "+f"(c[0]), "+f"(c[1]), "+f"(c[2]), "+f"(c[3])
        : "r"(a0), "r"(a1), "r"(a2), "r"(a3), "r"(b0), "r"(b1));
}

#define WS_STRIDE 68
#define SMEM_FLOATS (128 * WS_STRIDE + 64)

// ---------------- tf32 GEMM block body: out[M,128] = A[M,K] @ W[128,K]^T ----------------
template <int KDIM, bool NORM, bool ROWSCALE>
__device__ __forceinline__ void gemm_tf32_body(
    const float* __restrict__ A, const float* __restrict__ W,
    const float* __restrict__ bias, const float* __restrict__ rs,
    float* __restrict__ out, int M, float scale, int m0, float* smem) {

    const int tid = threadIdx.x, lane = tid & 31, w = tid >> 5;
    const int gid = lane >> 2, tig = lane & 3;
    const int wm = w & 1, wn = w >> 1;
    const int mbase = m0 + wm * 32;
    const int nbase = wn * 32;
    float* Ws = smem;
    float* ssq = smem + 128 * WS_STRIDE;

    float acc[2][4][4];
#pragma unroll
    for (int i = 0; i < 2; i++)
#pragma unroll
        for (int j = 0; j < 4; j++)
#pragma unroll
            for (int q = 0; q < 4; q++) acc[i][j][q] = 0.f;

    bool vlo[2], vhi[2];
    int rlo[2], rhi[2];
#pragma unroll
    for (int i = 0; i < 2; i++) {
        rlo[i] = mbase + i * 16 + gid;
        rhi[i] = rlo[i] + 8;
        vlo[i] = rlo[i] < M;
        vhi[i] = rhi[i] < M;
    }

    for (int kt = 0; kt < KDIM; kt += 64) {
        __syncthreads();
#pragma unroll
        for (int it = 0; it < 8; it++) {
            int idx = tid + it * 256;
            int n = idx >> 4, q = idx & 15;
            float4 v = *(const float4*)(W + (size_t)n * KDIM + kt + q * 4);
            *(float4*)&Ws[n * WS_STRIDE + q * 4] = v;
        }
        __syncthreads();
#pragma unroll
        for (int k8 = 0; k8 < 8; k8++) {
            int kg = kt + k8 * 8;
            unsigned af[2][4];
#pragma unroll
            for (int i = 0; i < 2; i++) {
                const float* Alo = A + (size_t)rlo[i] * KDIM + kg + tig;
                const float* Ahi = A + (size_t)rhi[i] * KDIM + kg + tig;
                float a0 = vlo[i] ? Alo[0] : 0.f;
                float a1 = vhi[i] ? Ahi[0] : 0.f;
                float a2 = vlo[i] ? Alo[4] : 0.f;
                float a3 = vhi[i] ? Ahi[4] : 0.f;
                af[i][0] = f2tf32(a0); af[i][1] = f2tf32(a1);
                af[i][2] = f2tf32(a2); af[i][3] = f2tf32(a3);
            }
#pragma unroll
            for (int j = 0; j < 4; j++) {
                int n = nbase + j * 8 + gid;
                unsigned b0 = f2tf32(Ws[n * WS_STRIDE + k8 * 8 + tig]);
                unsigned b1 = f2tf32(Ws[n * WS_STRIDE + k8 * 8 + tig + 4]);
#pragma unroll
                for (int i = 0; i < 2; i++)
                    mma_tf32(acc[i][j], af[i][0], af[i][1], af[i][2], af[i][3], b0, b1);
            }
        }
    }

    if (bias) {
#pragma unroll
        for (int j = 0; j < 4; j++) {
            int col = nbase + j * 8 + 2 * tig;
            float bv0 = bias[col], bv1 = bias[col + 1];
#pragma unroll
            for (int i = 0; i < 2; i++) {
                acc[i][j][0] += bv0; acc[i][j][1] += bv1;
                acc[i][j][2] += bv0; acc[i][j][3] += bv1;
            }
        }
    }

    float mul_lo[2], mul_hi[2];
#pragma unroll
    for (int i = 0; i < 2; i++) { mul_lo[i] = 1.f; mul_hi[i] = 1.f; }

    if (NORM) {
        __syncthreads();
        if (tid < 64) ssq[tid] = 0.f;
        __syncthreads();
#pragma unroll
        for (int i = 0; i < 2; i++) {
            float plo = 0.f, phi = 0.f;
#pragma unroll
            for (int j = 0; j < 4; j++) {
                plo += acc[i][j][0] * acc[i][j][0] + acc[i][j][1] * acc[i][j][1];
                phi += acc[i][j][2] * acc[i][j][2] + acc[i][j][3] * acc[i][j][3];
            }
            plo += __shfl_xor_sync(0xffffffffu, plo, 1);
            plo += __shfl_xor_sync(0xffffffffu, plo, 2);
            phi += __shfl_xor_sync(0xffffffffu, phi, 1);
            phi += __shfl_xor_sync(0xffffffffu, phi, 2);
            if (tig == 0) {
                atomicAdd(&ssq[wm * 32 + i * 16 + gid], plo);
                atomicAdd(&ssq[wm * 32 + i * 16 + gid + 8], phi);
            }
        }
        __syncthreads();
#pragma unroll
        for (int i = 0; i < 2; i++) {
            mul_lo[i] = scale / fmaxf(sqrtf(ssq[wm * 32 + i * 16 + gid]), 1e-12f);
            mul_hi[i] = scale / fmaxf(sqrtf(ssq[wm * 32 + i * 16 + gid + 8]), 1e-12f);
        }
    }
    if (ROWSCALE) {
#pragma unroll
        for (int i = 0; i < 2; i++) {
            if (vlo[i]) mul_lo[i] *= rs[rlo[i]];
            if (vhi[i]) mul_hi[i] *= rs[rhi[i]];
        }
    }

#pragma unroll
    for (int i = 0; i < 2; i++) {
#pragma unroll
        for (int j = 0; j < 4; j++) {
            int col = nbase + j * 8 + 2 * tig;
            if (vlo[i]) {
                float2 o = make_float2(acc[i][j][0] * mul_lo[i], acc[i][j][1] * mul_lo[i]);
                *(float2*)(out + (size_t)rlo[i] * CH + col) = o;
            }
            if (vhi[i]) {
                float2 o = make_float2(acc[i][j][2] * mul_hi[i], acc[i][j][3] * mul_hi[i]);
                *(float2*)(out + (size_t)rhi[i] * CH + col) = o;
            }
        }
    }
}

// ---------------- z2 body: 4 rows per block, depth-2 pipelined DRAM stream ----------------
// W22 (80KB) read from L2 once per 4 rows (was once per row) -> L2 traffic /4.
// 8 independent x2 loads in flight per thread (2 chunks x 4 rows).
__device__ __forceinline__ void z2_body4(const float* __restrict__ x2,
                                         const float* __restrict__ W22,
                                         int row0, float* smem) {
    const int tid = threadIdx.x, lane = tid & 31, wid = tid >> 5;
    const int NV = N_NODES / 4;   // 2500 float4 per row; 10 chunks of 256
    const float4* __restrict__ w0 = (const float4*)W22;
    const float4* __restrict__ w1 = (const float4*)(W22 + N_NODES);
    const float4* xr[4];
#pragma unroll
    for (int k = 0; k < 4; k++)
        xr[k] = (const float4*)(x2 + (size_t)(row0 + k) * N_NODES);

    float s0[4] = {0.f, 0.f, 0.f, 0.f}, s1[4] = {0.f, 0.f, 0.f, 0.f};
    float4 a[4], an[4], an2[4];

    // preload chunks 0 and 1 (both fully valid: 511 < 2500)
#pragma unroll
    for (int k = 0; k < 4; k++) a[k]  = xr[k][tid];
#pragma unroll
    for (int k = 0; k < 4; k++) an[k] = xr[k][256 + tid];

    int j = tid;
#pragma unroll
    for (int c = 0; c < 10; c++) {
        bool v = j < NV;
        int js = v ? j : 0;
        float4 b = w0[js], cc = w1[js];
        if (!v) { b = make_float4(0.f,0.f,0.f,0.f); cc = make_float4(0.f,0.f,0.f,0.f); }
        if (c < 8) {
            int jp = j + 512;
            int jps = (jp < NV) ? jp : 0;
#pragma unroll
            for (int k = 0; k < 4; k++) an2[k] = xr[k][jps];
        }
#pragma unroll
        for (int k = 0; k < 4; k++) {
            s0[k] += a[k].x * b.x  + a[k].y * b.y  + a[k].z * b.z  + a[k].w * b.w;
            s1[k] += a[k].x * cc.x + a[k].y * cc.y + a[k].z * cc.z + a[k].w * cc.w;
        }
#pragma unroll
        for (int k = 0; k < 4; k++) { a[k] = an[k]; an[k] = an2[k]; }
        j += 256;
    }

#pragma unroll
    for (int k = 0; k < 4; k++) {
#pragma unroll
        for (int d = 16; d; d >>= 1) {
            s0[k] += __shfl_xor_sync(0xffffffffu, s0[k], d);
            s1[k] += __shfl_xor_sync(0xffffffffu, s1[k], d);
        }
    }
    float* r0 = smem;        // [4][8]
    float* r1 = smem + 32;   // [4][8]
    if (lane == 0) {
#pragma unroll
        for (int k = 0; k < 4; k++) { r0[k * 8 + wid] = s0[k]; r1[k * 8 + wid] = s1[k]; }
    }
    __syncthreads();
    if (tid < 4) {
        float y0 = 0.f, y1 = 0.f;
#pragma unroll
        for (int q = 0; q < 8; q++) { y0 += r0[tid * 8 + q]; y1 += r1[tid * 8 + q]; }
        float n = fmaxf(sqrtf(y0 * y0 + y1 * y1), 1e-12f);
        g_z2c0[row0 + tid] = 0.8f * y0 / n;
    }
}

// ---------------- fatA: gemm1 + CSR fill + z2 blocks [0, Z2A_BLK) ----------------
#define GEMM_BLOCKS 157
#define FILL_BLOCKS 64
__global__ __launch_bounds__(256) void fatA_kernel(
    const float* __restrict__ x, const float* __restrict__ W2,
    const float* __restrict__ b2,
    const float* __restrict__ x2, const float* __restrict__ W22) {
    __shared__ float smem[SMEM_FLOATS];
    int b = blockIdx.x;
    if (b < GEMM_BLOCKS) {
        gemm_tf32_body<IN_DIM, true, false>(x, W2, b2, nullptr, g_h,
                                            N_NODES, 1.8f, b * 64, smem);
    } else if (b < GEMM_BLOCKS + FILL_BLOCKS) {
        int bb = b - GEMM_BLOCKS;
        for (int e = threadIdx.x + bb * 256; e < N_EDGES; e += FILL_BLOCKS * 256) {
            int t = g_tgt[e];
            int p = atomicAdd(&g_pos[t], 1);
            int w = g_off[t] + p;
            g_adj[w] = g_src[e];
            g_eid[w] = e;
        }
    } else {
        z2_body4(x2, W22, (b - GEMM_BLOCKS - FILL_BLOCKS) * 4, smem);
    }
}

// ---------------- fatB: gemm2 + z2 blocks [Z2A_BLK, Z2A_BLK+Z2B_BLK) ----------------
__global__ __launch_bounds__(256) void fatB_kernel(
    const float* __restrict__ Wg,
    const float* __restrict__ x2, const float* __restrict__ W22) {
    __shared__ float smem[SMEM_FLOATS];
    int b = blockIdx.x;
    if (b < GEMM_BLOCKS) {
        gemm_tf32_body<CH, false, true>(g_h, Wg, nullptr, g_dinv, g_xw,
                                        N_NODES, 1.0f, b * 64, smem);
    } else {
        z2_body4(x2, W22, (Z2A_BLK + (b - GEMM_BLOCKS)) * 4, smem);
    }
}

// ---------------- gather body ----------------
__device__ __forceinline__ void gather_body(const float* __restrict__ bg,
                                            int i, int c) {
    float di = g_dinv[i];
    float acc = g_xw[i * CH + c];
    int s0 = g_off[i], s1 = g_off[i + 1];
    int j = s0;
    for (; j + 4 <= s1; j += 4) {
        int a0 = g_adj[j], a1 = g_adj[j + 1], a2 = g_adj[j + 2], a3 = g_adj[j + 3];
        float v0 = g_xw[a0 * CH + c], v1 = g_xw[a1 * CH + c];
        float v2 = g_xw[a2 * CH + c], v3 = g_xw[a3 * CH + c];
        acc += (v0 + v1) + (v2 + v3);
    }
    for (; j < s1; j++) acc += g_xw[g_adj[j] * CH + c];
    g_z1[i * CH + c] = acc * di + bg[c];
}

// ---------------- fatC: gather + z2 blocks [Z2A_BLK+Z2B_BLK, 2500) ----------------
#define GATHER_BLOCKS 5000
__global__ __launch_bounds__(256) void fatC_kernel(
    const float* __restrict__ bg,
    const float* __restrict__ x2, const float* __restrict__ W22) {
    __shared__ float smem[SMEM_FLOATS];
    int b = blockIdx.x;
    if (b < Z2C_BLK) {
        z2_body4(x2, W22, (Z2A_BLK + Z2B_BLK + b) * 4, smem);
    } else {
        int g = b - Z2C_BLK;
        int node = g * 2 + (threadIdx.x >> 7);
        gather_body(bg, node, threadIdx.x & 127);
    }
}

// ---------------- decoder: warp per target node, CSR order, out[eid] ----------------
__global__ __launch_bounds__(256) void decoder_kernel(float* __restrict__ out) {
    int gtid = blockIdx.x * blockDim.x + threadIdx.x;
    if (gtid < N_NODES) { g_cnt[gtid] = 0; g_pos[gtid] = 0; }

    int node = gtid >> 5;
    int lane = threadIdx.x & 31;
    if (node >= N_NODES) return;
    float4 zc = *(const float4*)(g_z1 + (size_t)node * CH + lane * 4);
    float zc0 = g_z2c0[node];
    int s0 = g_off[node], s1 = g_off[node + 1];
    for (int j = s0; j < s1; j++) {
        int s = g_adj[j];
        const float4 a = *(const float4*)(g_z1 + (size_t)s * CH + lane * 4);
        float d = a.x * zc.x + a.y * zc.y + a.z * zc.z + a.w * zc.w;
#pragma unroll
        for (int o = 16; o; o >>= 1) d += __shfl_xor_sync(0xffffffffu, d, o);
        if (lane == 0) {
            float vn = g_z2c0[s] + zc0;
            float sf = 1.f / (1.f + __expf(-d));
            float sn = 1.f / (1.f + __expf(-vn));
            out[g_eid[j]] = sf * sf + (1.f - sf) * sn;
        }
    }
}

// ---------------- launch ----------------
extern "C" void kernel_launch(void* const* d_in, const int* in_sizes, int n_in,
                              void* d_out, int out_size) {
    const float* x    = (const float*)d_in[0];
    const float* x2   = (const float*)d_in[1];
    const float* W2   = (const float*)d_in[2];
    const float* b2   = (const float*)d_in[3];
    const float* Wg   = (const float*)d_in[4];
    const float* bg   = (const float*)d_in[5];
    const float* W22  = (const float*)d_in[6];
    const int*   edge = (const int*)d_in[7];
    float* out = (float*)d_out;

    cvt_count_kernel<<<(N_EDGES + 255) / 256, 256>>>(edge);
    scan_kernel<<<1, 1024>>>();

    fatA_kernel<<<GEMM_BLOCKS + FILL_BLOCKS + Z2A_BLK, 256>>>(x, W2, b2, x2, W22);
    fatB_kernel<<<GEMM_BLOCKS + Z2B_BLK, 256>>>(Wg, x2, W22);
    fatC_kernel<<<Z2C_BLK + GATHER_BLOCKS, 256>>>(bg, x2, W22);

    decoder_kernel<<<(N_NODES * 32 + 255) / 256, 256>>>(out);
}